// round 9
// baseline (speedup 1.0000x reference)
#include <cuda_runtime.h>
#include <cstdint>

// VoxelBracketPredictor_v2 — 2-kernel pipeline:
//  k0 bounds: segment boundaries (int4 scan of sorted segment_ids)
//  k1 fused:  CTA = 8 CONTIGUOUS samples (preserves DRAM streaming locality).
//             pool: cp.async ring, warp per sample.
//             coarse MLP: CTA-cooperative.
//             refinement: in-CTA class-run cooperative passes (samples sorted
//             by class in SMEM; weights streamed once per class-run pass by
//             all 256 threads -> ~2x less L2 traffic than warp-per-sample).

#define EPS 1e-5f
#define BMAX 4096

__device__ int g_bound[BMAX + 1];

// ---------------- kernel 0: boundaries ----------------
__global__ void bounds_kernel(const int* __restrict__ seg, int N, int B) {
    int t = blockIdx.x * blockDim.x + threadIdx.x;
    int i = t * 4;
    if (i >= N) return;
    int vals[4];
    if (i + 4 <= N) {
        int4 v = *(const int4*)(seg + i);
        vals[0] = v.x; vals[1] = v.y; vals[2] = v.z; vals[3] = v.w;
    } else {
        for (int j = 0; j < 4; j++) vals[j] = (i + j < N) ? seg[i + j] : vals[j > 0 ? j - 1 : 0];
    }
    int prev = (i == 0) ? -1 : seg[i - 1];
    int lim = min(4, N - i);
    for (int j = 0; j < lim; j++) {
        int cur = vals[j];
        for (int b = prev + 1; b <= cur; b++) g_bound[b] = i + j;
        prev = cur;
    }
    if (i + 4 >= N)
        for (int b = prev + 1; b <= B; b++) g_bound[b] = N;
}

__device__ __forceinline__ float warpSum(float v) {
#pragma unroll
    for (int o = 16; o; o >>= 1) v += __shfl_xor_sync(0xffffffffu, v, o);
    return v;
}

__device__ __forceinline__ uint32_t smem_u32(const void* p) {
    uint32_t a;
    asm("{ .reg .u64 t; cvta.to.shared.u64 t, %1; cvt.u32.u64 %0, t; }" : "=r"(a) : "l"(p));
    return a;
}
__device__ __forceinline__ void cp_async16(uint32_t saddr, const void* gaddr) {
    asm volatile("cp.async.cg.shared.global [%0], [%1], 16;" :: "r"(saddr), "l"(gaddr));
}
#define CP_COMMIT() asm volatile("cp.async.commit_group;" ::)
#define CP_WAIT(n)  asm volatile("cp.async.wait_group %0;" :: "n"(n))

// ---------------- kernel 1: fused pool + MLP ----------------
__global__ __launch_bounds__(256) void fused_kernel(
    const float* __restrict__ feat, const int* __restrict__ cls,
    const float* __restrict__ cW1, const float* __restrict__ cb1,
    const float* __restrict__ cg1, const float* __restrict__ cbe1,
    const float* __restrict__ cW2, const float* __restrict__ cb2,
    const float* __restrict__ cg2, const float* __restrict__ cbe2,
    const float* __restrict__ cW3, const float* __restrict__ cb3,
    const float* __restrict__ rW1, const float* __restrict__ rb1,
    const float* __restrict__ rg1, const float* __restrict__ rbe1,
    const float* __restrict__ rW2, const float* __restrict__ rb2,
    const float* __restrict__ rg2, const float* __restrict__ rbe2,
    const float* __restrict__ rW3, const float* __restrict__ rb3,
    float* __restrict__ out, int B)
{
    __shared__ float smem_all[9216];     // pool ring (8 warps x 3 x 384) / MLP acts
    __shared__ float sin_[8][96];        // pooled inputs
    __shared__ float sstat[8][2];
    __shared__ int   sslot[8];           // sample slots sorted by class
    __shared__ int   srun[5];            // class run offsets
    __shared__ int   scls8[8];           // per-slot class

    const int tid = threadIdx.x, lane = tid & 31, w = tid >> 5;
    const int b = blockIdx.x * 8 + w;
    const bool valid = b < B;
    const int bc = valid ? b : B - 1;

    if (tid < 8) scls8[tid] = cls[min(blockIdx.x * 8 + tid, B - 1)];

    // ================= phase 1: cp.async mean pool (warp per sample) ========
    {
        const int start = g_bound[bc], end = g_bound[bc + 1];
        const int nr = end - start;
        const float* gsrc = feat + (size_t)start * 96;
        float* sb = smem_all + w * 1152;             // 3 bufs x 384 floats
        const uint32_t sb_u = smem_u32(sb);

        const int T = (nr + 3) >> 2;                 // 4-row chunks
        float a0 = 0.f, a1 = 0.f, a2 = 0.f;

        #define ISSUE(i)                                                              \
        {                                                                             \
            const int _i = (i);                                                       \
            const int _cnt = min(4, nr - _i * 4) * 24;                                \
            const uint32_t _sbase = sb_u + (uint32_t)(_i % 3) * 1536u;                \
            const float* _g = gsrc + (size_t)_i * 384;                                \
            if (lane < _cnt)      cp_async16(_sbase + lane * 16u,        _g + lane * 4);        \
            if (lane + 32 < _cnt) cp_async16(_sbase + (lane + 32) * 16u, _g + (lane + 32) * 4); \
            if (lane + 64 < _cnt) cp_async16(_sbase + (lane + 64) * 16u, _g + (lane + 64) * 4); \
            CP_COMMIT();                                                              \
        }

        if (T > 0) ISSUE(0);
        if (T > 1) ISSUE(1);
        if (T > 2) ISSUE(2);

        for (int i = 0; i < T; i++) {
            const int after = T - 1 - i;
            if (after >= 2)      CP_WAIT(2);
            else if (after == 1) CP_WAIT(1);
            else                 CP_WAIT(0);
            __syncwarp();

            const float* bp = sb + (i % 3) * 384;
            const int rows = min(4, nr - i * 4);
            if (rows == 4) {
#pragma unroll
                for (int r = 0; r < 4; r++) {
                    a0 += bp[r * 96 + lane];
                    a1 += bp[r * 96 + 32 + lane];
                    a2 += bp[r * 96 + 64 + lane];
                }
            } else {
                for (int r = 0; r < rows; r++) {
                    a0 += bp[r * 96 + lane];
                    a1 += bp[r * 96 + 32 + lane];
                    a2 += bp[r * 96 + 64 + lane];
                }
            }
            __syncwarp();
            if (i + 3 < T) ISSUE(i + 3);
        }
        #undef ISSUE

        const float inv = 1.f / fmaxf((float)nr, 1.f);
        sin_[w][lane]      = a0 * inv;
        sin_[w][lane + 32] = a1 * inv;
        sin_[w][lane + 64] = a2 * inv;
    }
    __syncthreads();

    // class-run sort (visible by the sync after coarse L1 matmul)
    if (tid == 0) {
        int cnt[4] = {0, 0, 0, 0};
        for (int s = 0; s < 8; s++) cnt[scls8[s]]++;
        srun[0] = 0;
        for (int k = 0; k < 4; k++) srun[k + 1] = srun[k] + cnt[k];
        int pos[4] = {srun[0], srun[1], srun[2], srun[3]};
        for (int s = 0; s < 8; s++) sslot[pos[scls8[s]]++] = s;
    }

    float* actA = smem_all;          // 8 x 256
    float* actB = smem_all + 2048;   // 8 x 128
    #define ACTA(s, f) actA[(s) * 256 + (f)]
    #define ACTB(s, f) actB[(s) * 128 + (f)]

    // ================= coarse L1 (96 -> 256), CTA-cooperative ==============
    float acc[8];
    {
        const int f = tid;
        const float bv = cb1[f];
#pragma unroll
        for (int s = 0; s < 8; s++) acc[s] = bv;
#pragma unroll 2
        for (int c = 0; c < 96; c += 4) {
            float w0 = cW1[(c + 0) * 256 + f];
            float w1 = cW1[(c + 1) * 256 + f];
            float w2 = cW1[(c + 2) * 256 + f];
            float w3 = cW1[(c + 3) * 256 + f];
#pragma unroll
            for (int s = 0; s < 8; s++) {
                float4 x = *(const float4*)(&sin_[s][c]);
                acc[s] = fmaf(x.x, w0, acc[s]);
                acc[s] = fmaf(x.y, w1, acc[s]);
                acc[s] = fmaf(x.z, w2, acc[s]);
                acc[s] = fmaf(x.w, w3, acc[s]);
            }
        }
#pragma unroll
        for (int s = 0; s < 8; s++) ACTA(s, f) = acc[s];
    }
    __syncthreads();
    {
        float sum = 0.f, sq = 0.f;
#pragma unroll
        for (int j = 0; j < 8; j++) {
            float x = ACTA(w, lane + 32 * j);
            sum += x; sq = fmaf(x, x, sq);
        }
        sum = warpSum(sum); sq = warpSum(sq);
        if (lane == 0) {
            float m = sum * (1.f / 256.f);
            float v = sq * (1.f / 256.f) - m * m;
            sstat[w][0] = m; sstat[w][1] = rsqrtf(v + EPS);
        }
    }
    __syncthreads();
    {
        const int f = tid;
        const float g = cg1[f], e = cbe1[f];
#pragma unroll
        for (int s = 0; s < 8; s++) {
            float m = sstat[s][0], r = sstat[s][1];
            ACTA(s, f) = fmaxf(fmaf((acc[s] - m) * r, g, e), 0.f);
        }
    }
    __syncthreads();

    // ================= coarse L2 (256 -> 128), CTA-cooperative =============
    float acc2[4];
    const int fL2 = tid & 127, sh = tid >> 7;
    {
        const float bv = cb2[fL2];
#pragma unroll
        for (int i = 0; i < 4; i++) acc2[i] = bv;
#pragma unroll 2
        for (int c = 0; c < 256; c += 4) {
            float w0 = cW2[(c + 0) * 128 + fL2];
            float w1 = cW2[(c + 1) * 128 + fL2];
            float w2 = cW2[(c + 2) * 128 + fL2];
            float w3 = cW2[(c + 3) * 128 + fL2];
#pragma unroll
            for (int i = 0; i < 4; i++) {
                float4 x = *(const float4*)(&ACTA(sh * 4 + i, c));
                acc2[i] = fmaf(x.x, w0, acc2[i]);
                acc2[i] = fmaf(x.y, w1, acc2[i]);
                acc2[i] = fmaf(x.z, w2, acc2[i]);
                acc2[i] = fmaf(x.w, w3, acc2[i]);
            }
        }
#pragma unroll
        for (int i = 0; i < 4; i++) ACTB(sh * 4 + i, fL2) = acc2[i];
    }
    __syncthreads();
    {
        float sum = 0.f, sq = 0.f;
#pragma unroll
        for (int j = 0; j < 4; j++) {
            float x = ACTB(w, lane + 32 * j);
            sum += x; sq = fmaf(x, x, sq);
        }
        sum = warpSum(sum); sq = warpSum(sq);
        if (lane == 0) {
            float m = sum * (1.f / 128.f);
            float v = sq * (1.f / 128.f) - m * m;
            sstat[w][0] = m; sstat[w][1] = rsqrtf(v + EPS);
        }
    }
    __syncthreads();
    {
        const float g = cg2[fL2], e = cbe2[fL2];
#pragma unroll
        for (int i = 0; i < 4; i++) {
            int s = sh * 4 + i;
            float m = sstat[s][0], r = sstat[s][1];
            ACTB(s, fL2) = fmaxf(fmaf((acc2[i] - m) * r, g, e), 0.f);
        }
    }
    __syncthreads();

    // ================= coarse L3: 128 -> 3 (warp w -> sample w) ============
    float p0 = 0.f, p1 = 0.f, p2 = 0.f;
#pragma unroll
    for (int t = 0; t < 4; t++) {
        int c = lane + 32 * t;
        float x = ACTB(w, c);
        p0 = fmaf(x, cW3[c * 3 + 0], p0);
        p1 = fmaf(x, cW3[c * 3 + 1], p1);
        p2 = fmaf(x, cW3[c * 3 + 2], p2);
    }
    p0 = warpSum(p0) + cb3[0];
    p1 = warpSum(p1) + cb3[1];
    p2 = warpSum(p2) + cb3[2];

    // ================= refine L1: 96 -> 128, class-run cooperative =========
    // 128 feats x 2 sample slots per pass; weights streamed once per pass.
    {
        const int fR = fL2, hR = sh;     // f = tid&127, parity = tid>>7
#pragma unroll
        for (int k = 0; k < 4; k++) {
            const int lo = srun[k], hi = srun[k + 1];
            if (lo == hi) continue;
            const float* W = rW1 + k * 96 * 128;
            const float bv = rb1[k * 128 + fR];
            for (int base = lo; base < hi; base += 2) {
                const int j = base + hR;
                if (j < hi) {
                    const int s = sslot[j];
                    float a = bv, bacc = 0.f;
                    for (int c = 0; c < 96; c += 4) {
                        float4 x = *(const float4*)(&sin_[s][c]);
                        a    = fmaf(x.x, W[(c + 0) * 128 + fR], a);
                        bacc = fmaf(x.y, W[(c + 1) * 128 + fR], bacc);
                        a    = fmaf(x.z, W[(c + 2) * 128 + fR], a);
                        bacc = fmaf(x.w, W[(c + 3) * 128 + fR], bacc);
                    }
                    ACTA(s, fR) = a + bacc;   // raw pre-LN (reuse actA, stride 256)
                }
            }
        }
    }
    __syncthreads();
    {   // LN stats over 128 (warp w -> sample w)
        float sum = 0.f, sq = 0.f;
#pragma unroll
        for (int j = 0; j < 4; j++) {
            float x = ACTA(w, lane + 32 * j);
            sum += x; sq = fmaf(x, x, sq);
        }
        sum = warpSum(sum); sq = warpSum(sq);
        if (lane == 0) {
            float m = sum * (1.f / 128.f);
            float v = sq * (1.f / 128.f) - m * m;
            sstat[w][0] = m; sstat[w][1] = rsqrtf(v + EPS);
        }
    }
    __syncthreads();
    {   // apply LN+ReLU, class-indexed gamma/beta: thread (f=fL2) x 4 samples
#pragma unroll
        for (int i = 0; i < 4; i++) {
            const int s = sh * 4 + i;
            const int kk = scls8[s];
            const float g = rg1[kk * 128 + fL2], e = rbe1[kk * 128 + fL2];
            ACTA(s, fL2) = fmaxf(fmaf((ACTA(s, fL2) - sstat[s][0]) * sstat[s][1], g, e), 0.f);
        }
    }
    __syncthreads();

    // ================= refine L2: 128 -> 64, class-run cooperative =========
    // 64 feats x 4 sample slots per pass.
    {
        const int fS = tid & 63, qS = tid >> 6;
#pragma unroll
        for (int k = 0; k < 4; k++) {
            const int lo = srun[k], hi = srun[k + 1];
            if (lo == hi) continue;
            const float* W = rW2 + k * 128 * 64;
            const float bv = rb2[k * 64 + fS];
            for (int base = lo; base < hi; base += 4) {
                const int j = base + qS;
                if (j < hi) {
                    const int s = sslot[j];
                    float a = bv, bacc = 0.f;
                    for (int c = 0; c < 128; c += 4) {
                        float4 x = *(const float4*)(&ACTA(s, c));
                        a    = fmaf(x.x, W[(c + 0) * 64 + fS], a);
                        bacc = fmaf(x.y, W[(c + 1) * 64 + fS], bacc);
                        a    = fmaf(x.z, W[(c + 2) * 64 + fS], a);
                        bacc = fmaf(x.w, W[(c + 3) * 64 + fS], bacc);
                    }
                    ACTB(s, fS) = a + bacc;   // raw pre-LN (stride 128)
                }
            }
        }
    }
    __syncthreads();
    {   // LN stats over 64
        float x0 = ACTB(w, lane), x1 = ACTB(w, lane + 32);
        float su = warpSum(x0 + x1);
        float sq = warpSum(fmaf(x0, x0, x1 * x1));
        if (lane == 0) {
            float m = su * (1.f / 64.f);
            float v = sq * (1.f / 64.f) - m * m;
            sstat[w][0] = m; sstat[w][1] = rsqrtf(v + EPS);
        }
    }
    __syncthreads();
    {   // apply, class-indexed: thread (f=tid&63) x 2 samples
        const int fS = tid & 63, qS = tid >> 6;
#pragma unroll
        for (int i = 0; i < 2; i++) {
            const int s = qS * 2 + i;
            const int kk = scls8[s];
            const float g = rg2[kk * 64 + fS], e = rbe2[kk * 64 + fS];
            ACTB(s, fS) = fmaxf(fmaf((ACTB(s, fS) - sstat[s][0]) * sstat[s][1], g, e), 0.f);
        }
    }
    __syncthreads();

    // ================= refine L3: 64 -> 3 (warp w -> sample w), write ======
    {
        const int kk = scls8[w];
        const float* W3 = rW3 + kk * 192;
        float q0 = 0.f, q1 = 0.f, q2 = 0.f;
#pragma unroll
        for (int t = 0; t < 2; t++) {
            int c = lane + 32 * t;
            float x = ACTB(w, c);
            q0 = fmaf(x, W3[c * 3 + 0], q0);
            q1 = fmaf(x, W3[c * 3 + 1], q1);
            q2 = fmaf(x, W3[c * 3 + 2], q2);
        }
        q0 = warpSum(q0) + rb3[kk * 3 + 0];
        q1 = warpSum(q1) + rb3[kk * 3 + 1];
        q2 = warpSum(q2) + rb3[kk * 3 + 2];

        if (valid && lane < 3) {
            float pc = (lane == 0) ? p0 : (lane == 1) ? p1 : p2;
            float qc = (lane == 0) ? q0 : (lane == 1) ? q1 : q2;
            out[b * 3 + lane] = pc + qc;
        }
    }
    #undef ACTA
    #undef ACTB
}

// ---------------- launch ----------------
extern "C" void kernel_launch(void* const* d_in, const int* in_sizes, int n_in,
                              void* d_out, int out_size) {
    const float* feat = (const float*)d_in[0];
    const int*   seg  = (const int*)d_in[1];
    const int*   cls  = (const int*)d_in[2];
    const int N = in_sizes[1];
    const int B = in_sizes[2];

    bounds_kernel<<<(N / 4 + 255) / 256, 256>>>(seg, N, B);
    fused_kernel<<<(B + 7) / 8, 256>>>(
        feat, cls,
        (const float*)d_in[3],  (const float*)d_in[4],  (const float*)d_in[5],  (const float*)d_in[6],
        (const float*)d_in[7],  (const float*)d_in[8],  (const float*)d_in[9],  (const float*)d_in[10],
        (const float*)d_in[11], (const float*)d_in[12],
        (const float*)d_in[13], (const float*)d_in[14], (const float*)d_in[15], (const float*)d_in[16],
        (const float*)d_in[17], (const float*)d_in[18], (const float*)d_in[19], (const float*)d_in[20],
        (const float*)d_in[21], (const float*)d_in[22],
        (float*)d_out, B);
}